// round 2
// baseline (speedup 1.0000x reference)
#include <cuda_runtime.h>
#include <cuda_bf16.h>
#include <math.h>

// Problem constants (validated against in_sizes at launch)
#define F 128          // feature dim (HID = F_IN = 128)
#define MAXN 50000
#define MAXE 500000
#define MAXT (MAXE + MAXN)

// ---------------- scratch (static device globals; no allocation) -------------
__device__ float    g_xl[(size_t)MAXN * F];     // x @ Wl + bl
__device__ float    g_xr[(size_t)MAXN * F];     // x @ Wr + br
__device__ float    g_logits[MAXT];
__device__ float    g_p[MAXT];
__device__ int      g_src[MAXT];
__device__ int      g_dst[MAXT];
__device__ unsigned g_menc[MAXN];               // order-preserving float encoding
__device__ float    g_denom[MAXN];
__device__ float    g_acc[F];                   // global weighted-sum accumulator
__device__ int      g_is64;                     // edge_index dtype flag

// order-preserving float<->uint for atomicMax on floats (incl. negatives)
__device__ __forceinline__ unsigned fenc(float f) {
    unsigned u = __float_as_uint(f);
    return (u >> 31) ? ~u : (u | 0x80000000u);
}
__device__ __forceinline__ float fdec(unsigned u) {
    return (u >> 31) ? __uint_as_float(u & 0x7FFFFFFFu) : __uint_as_float(~u);
}

// ---------------- dtype detection (reads only first 512 bytes — safe) -------
__global__ void detect_dtype(const void* ei, int nE, int nN) {
    const long long* e64 = (const long long*)ei;
    int ok = 1;
    int lim = nE < 64 ? nE : 64;
    for (int i = 0; i < lim; i++) {
        long long v = e64[i];
        if (v < 0 || v >= (long long)nN) { ok = 0; break; }
    }
    g_is64 = ok;
}

// ---------------- init ----------------
__global__ void init_kernel(int nN) {
    int i = blockIdx.x * blockDim.x + threadIdx.x;
    if (i < nN) { g_menc[i] = 0u; g_denom[i] = 0.f; }  // 0 == fenc of most-negative
    if (i < F) g_acc[i] = 0.f;
}

// ---------------- GEMM: [xl|xr] = x @ [Wl|Wr] + [bl|br] ----------------
// Block: 32 rows x 256 cols (128 Wl + 128 Wr), 256 threads.
// Thread: 8 rows x 4 cols accumulators; x tile in smem, W streamed via L2.
__global__ void __launch_bounds__(256) gemm_xlxr(
    const float* __restrict__ x,
    const float* __restrict__ Wl, const float* __restrict__ bl,
    const float* __restrict__ Wr, const float* __restrict__ br,
    int n)
{
    __shared__ float4 xs[32 * 32];  // 32 rows x 128 floats = 16 KB
    const int tid  = threadIdx.x;
    const int row0 = blockIdx.x << 5;

    #pragma unroll
    for (int i = tid; i < 1024; i += 256) {
        int r = i >> 5, q = i & 31;
        int row = row0 + r;
        xs[i] = (row < n) ? reinterpret_cast<const float4*>(x)[(size_t)row * 32 + q]
                          : make_float4(0.f, 0.f, 0.f, 0.f);
    }
    __syncthreads();

    const int g    = tid & 63;          // column group: 0..31 -> Wl, 32..63 -> Wr
    const int rset = tid >> 6;          // 0..3 -> rows rset*8 .. rset*8+7
    const bool isL = (g < 32);
    const int  gc  = g & 31;
    const float4* W4 = reinterpret_cast<const float4*>(isL ? Wl : Wr);

    float4 acc[8];
    #pragma unroll
    for (int r = 0; r < 8; r++) acc[r] = make_float4(0.f, 0.f, 0.f, 0.f);

    const float* xb = reinterpret_cast<const float*>(xs) + (rset * 8) * F;

    #pragma unroll 4
    for (int k0 = 0; k0 < F; k0 += 4) {
        float4 xv[8];
        #pragma unroll
        for (int r = 0; r < 8; r++)
            xv[r] = *reinterpret_cast<const float4*>(xb + r * F + k0);
        #pragma unroll
        for (int kk = 0; kk < 4; kk++) {
            float4 w = __ldg(&W4[(size_t)(k0 + kk) * 32 + gc]);
            #pragma unroll
            for (int r = 0; r < 8; r++) {
                float xvv = (kk == 0) ? xv[r].x : (kk == 1) ? xv[r].y
                          : (kk == 2) ? xv[r].z : xv[r].w;
                acc[r].x += xvv * w.x;
                acc[r].y += xvv * w.y;
                acc[r].z += xvv * w.z;
                acc[r].w += xvv * w.w;
            }
        }
    }

    float4 b = __ldg(&reinterpret_cast<const float4*>(isL ? bl : br)[gc]);
    float4* outp = reinterpret_cast<float4*>(isL ? g_xl : g_xr);
    #pragma unroll
    for (int r = 0; r < 8; r++) {
        int row = row0 + rset * 8 + r;
        if (row < n) {
            float4 v = acc[r];
            v.x += b.x; v.y += b.y; v.z += b.z; v.w += b.w;
            outp[(size_t)row * 32 + gc] = v;
        }
    }
}

// ---------------- pass 1: per-edge logits + segment max ----------------
// One warp per edge; lane l covers dims 4l..4l+3 (float4, fully coalesced).
__global__ void __launch_bounds__(256) edge_pass1(
    const void* __restrict__ ei_raw, const float* __restrict__ att,
    int nE, int nN)
{
    const int lane   = threadIdx.x & 31;
    const int warp   = (blockIdx.x * blockDim.x + threadIdx.x) >> 5;
    const int nwarps = (gridDim.x * blockDim.x) >> 5;
    const int total  = nE + nN;
    const int is64   = g_is64;
    const long long* e64 = (const long long*)ei_raw;
    const int*       e32 = (const int*)ei_raw;

    const float4 a = reinterpret_cast<const float4*>(att)[lane];
    const float4* xl4 = reinterpret_cast<const float4*>(g_xl);
    const float4* xr4 = reinterpret_cast<const float4*>(g_xr);

    for (int e = warp; e < total; e += nwarps) {
        int s, d;
        if (e < nE) {
            if (is64) { s = (int)e64[e]; d = (int)e64[nE + e]; }
            else      { s = e32[e];      d = e32[nE + e];      }
        } else {
            s = e - nE; d = s;
        }

        float4 u = xl4[(size_t)s * 32 + lane];
        float4 v = xr4[(size_t)d * 32 + lane];
        float z, sum;
        z = u.x + v.x; z = z > 0.f ? z : 0.2f * z; sum  = a.x * z;
        z = u.y + v.y; z = z > 0.f ? z : 0.2f * z; sum += a.y * z;
        z = u.z + v.z; z = z > 0.f ? z : 0.2f * z; sum += a.z * z;
        z = u.w + v.w; z = z > 0.f ? z : 0.2f * z; sum += a.w * z;

        #pragma unroll
        for (int off = 16; off > 0; off >>= 1)
            sum += __shfl_xor_sync(0xffffffffu, sum, off);

        if (lane == 0) {
            g_logits[e] = sum;
            g_src[e] = s;
            g_dst[e] = d;
            atomicMax(&g_menc[d], fenc(sum));
        }
    }
}

// ---------------- pass 2: p = exp(logit - m[dst]); denom[dst] += p -------
__global__ void __launch_bounds__(256) edge_pass2(int total) {
    int e = blockIdx.x * blockDim.x + threadIdx.x;
    if (e >= total) return;
    int d = g_dst[e];
    float m = fdec(g_menc[d]);
    float p = __expf(g_logits[e] - m);
    g_p[e] = p;
    atomicAdd(&g_denom[d], p);
}

// ---------------- pass 3: acc += (p/denom[dst]) * xl[src] (global 128-vec) --
__global__ void __launch_bounds__(256) edge_pass3(int total) {
    __shared__ float sacc[F];
    const int tid = threadIdx.x;
    if (tid < F) sacc[tid] = 0.f;
    __syncthreads();

    const int lane   = tid & 31;
    const int warp   = (blockIdx.x * blockDim.x + tid) >> 5;
    const int nwarps = (gridDim.x * blockDim.x) >> 5;
    const float4* xl4 = reinterpret_cast<const float4*>(g_xl);

    float4 acc = make_float4(0.f, 0.f, 0.f, 0.f);
    for (int e = warp; e < total; e += nwarps) {
        int s = 0; float w = 0.f;
        if (lane == 0) {
            s = g_src[e];
            w = g_p[e] / g_denom[g_dst[e]];
        }
        s = __shfl_sync(0xffffffffu, s, 0);
        w = __shfl_sync(0xffffffffu, w, 0);
        float4 u = xl4[(size_t)s * 32 + lane];
        acc.x += w * u.x; acc.y += w * u.y; acc.z += w * u.z; acc.w += w * u.w;
    }

    atomicAdd(&sacc[lane * 4 + 0], acc.x);
    atomicAdd(&sacc[lane * 4 + 1], acc.y);
    atomicAdd(&sacc[lane * 4 + 2], acc.z);
    atomicAdd(&sacc[lane * 4 + 3], acc.w);
    __syncthreads();
    if (tid < F) atomicAdd(&g_acc[tid], sacc[tid]);
}

// ---------------- finalize: mean + bias + BN + pool + classifier + softmax --
__global__ void finalize(
    const float* __restrict__ bias1,
    const float* __restrict__ gamma, const float* __restrict__ beta,
    const float* __restrict__ mean,  const float* __restrict__ var,
    const float* __restrict__ Wc,    const float* __restrict__ bc,
    float* __restrict__ out, int nN)
{
    __shared__ float sg[F];
    __shared__ float sl[5];
    const int d = threadIdx.x;

    float gv = g_acc[d] / (float)nN + bias1[d];
    gv = (gv - mean[d]) * rsqrtf(var[d] + 1e-5f) * gamma[d] + beta[d];
    sg[d] = gv;
    __syncthreads();

    if (d < 5) {
        float s = bc[d];
        #pragma unroll 8
        for (int k = 0; k < F; k++) s += sg[k] * Wc[k * 5 + d];
        sl[d] = s;
    }
    __syncthreads();

    if (d == 0) {
        float mx = sl[0];
        #pragma unroll
        for (int c = 1; c < 5; c++) mx = fmaxf(mx, sl[c]);
        float e[5], sum = 0.f;
        #pragma unroll
        for (int c = 0; c < 5; c++) { e[c] = expf(sl[c] - mx); sum += e[c]; }
        #pragma unroll
        for (int c = 0; c < 5; c++) out[c] = e[c] / sum;
    }
}

// ---------------- launch ----------------
extern "C" void kernel_launch(void* const* d_in, const int* in_sizes, int n_in,
                              void* d_out, int out_size)
{
    const float* x     = (const float*)d_in[0];
    const void*  ei    = d_in[1];
    const float* Wl    = (const float*)d_in[2];
    const float* bl    = (const float*)d_in[3];
    const float* Wr    = (const float*)d_in[4];
    const float* br    = (const float*)d_in[5];
    const float* att   = (const float*)d_in[6];
    const float* bias1 = (const float*)d_in[7];
    const float* gamma = (const float*)d_in[8];
    const float* beta  = (const float*)d_in[9];
    const float* mean  = (const float*)d_in[10];
    const float* var   = (const float*)d_in[11];
    const float* Wc    = (const float*)d_in[12];
    const float* bc    = (const float*)d_in[13];
    float* out = (float*)d_out;

    const int nN = in_sizes[0] / F;     // 50000
    const int nE = in_sizes[1] / 2;     // 500000
    const int total = nE + nN;

    detect_dtype<<<1, 1>>>(ei, nE, nN);
    init_kernel<<<(nN + 255) / 256, 256>>>(nN);
    gemm_xlxr<<<(nN + 31) / 32, 256>>>(x, Wl, bl, Wr, br, nN);
    edge_pass1<<<2368, 256>>>(ei, att, nE, nN);
    edge_pass2<<<(total + 255) / 256, 256>>>(total);
    edge_pass3<<<2368, 256>>>(total);
    finalize<<<1, F>>>(bias1, gamma, beta, mean, var, Wc, bc, out, nN);
}

// round 3
// speedup vs baseline: 1.4301x; 1.4301x over previous
#include <cuda_runtime.h>
#include <cuda_bf16.h>
#include <math.h>

#define F 128
#define MAXN 50000
#define MAXE 500000
#define MAXT (MAXE + MAXN)

// ---------------- scratch ----------------
__device__ __nv_bfloat162 g_xlb[(size_t)MAXN * 64];   // xl in bf16 (pairs)
__device__ __nv_bfloat162 g_xrb[(size_t)MAXN * 64];   // xr in bf16 (pairs)
__device__ float    g_logits[MAXT];
__device__ float    g_p[MAXT];
__device__ int      g_src[MAXT];
__device__ int      g_dst[MAXT];
__device__ unsigned g_menc[MAXN];
__device__ float    g_denom[MAXN];
__device__ float    g_acc[F];
__device__ int      g_is64;

__device__ __forceinline__ unsigned fenc(float f) {
    unsigned u = __float_as_uint(f);
    return (u >> 31) ? ~u : (u | 0x80000000u);
}
__device__ __forceinline__ float fdec(unsigned u) {
    return (u >> 31) ? __uint_as_float(u & 0x7FFFFFFFu) : __uint_as_float(~u);
}

__device__ __forceinline__ unsigned f2tf(float f) {
    unsigned r;
    asm("cvt.rna.tf32.f32 %0, %1;" : "=r"(r) : "f"(f));
    return r;
}

__device__ __forceinline__ void mma_tf32(float* c,
    unsigned a0, unsigned a1, unsigned a2, unsigned a3,
    unsigned b0, unsigned b1)
{
    asm volatile(
        "mma.sync.aligned.m16n8k8.row.col.f32.tf32.tf32.f32 "
        "{%0,%1,%2,%3}, {%4,%5,%6,%7}, {%8,%9}, {%0,%1,%2,%3};"
        : "+f"(c[0]), "+f"(c[1]), "+f"(c[2]), "+f"(c[3])
        : "r"(a0), "r"(a1), "r"(a2), "r"(a3), "r"(b0), "r"(b1));
}

// ---------------- dtype detection ----------------
__global__ void detect_dtype(const void* ei, int nE, int nN) {
    const long long* e64 = (const long long*)ei;
    int ok = 1;
    int lim = nE < 64 ? nE : 64;
    for (int i = 0; i < lim; i++) {
        long long v = e64[i];
        if (v < 0 || v >= (long long)nN) { ok = 0; break; }
    }
    g_is64 = ok;
}

// ---------------- init ----------------
__global__ void init_kernel(int nN) {
    int i = blockIdx.x * blockDim.x + threadIdx.x;
    if (i < nN) { g_menc[i] = 0u; g_denom[i] = 0.f; }
    if (i < F) g_acc[i] = 0.f;
}

// ---------------- tf32 tensor-core GEMM ----------------
// [xl|xr](bf16) = x @ [Wl|Wr] + [bl|br]
// Block: 128 rows x 256 cols, 8 warps (warp w -> rows w*16..w*16+15, all 256 cols).
// W (tf32) staged in dynamic smem, stride 264 words (bank-conflict-free B frags).
#define WS_STRIDE 264
#define GEMM_SMEM (128 * WS_STRIDE * 4)

__global__ void __launch_bounds__(256) gemm_tf32(
    const float* __restrict__ x,
    const float* __restrict__ Wl, const float* __restrict__ bl,
    const float* __restrict__ Wr, const float* __restrict__ br,
    int n)
{
    extern __shared__ unsigned Ws[];   // [128][264] tf32 words
    const int tid = threadIdx.x;

    // stage W = [Wl | Wr] as tf32
    for (int i = tid; i < 128 * 256; i += 256) {
        int k = i >> 8, nn = i & 255;
        float v = (nn < 128) ? Wl[k * 128 + nn] : Wr[k * 128 + (nn - 128)];
        Ws[k * WS_STRIDE + nn] = f2tf(v);
    }
    __syncthreads();

    const int warp = tid >> 5, lane = tid & 31;
    const int g  = lane >> 2;          // 0..7
    const int tk = lane & 3;           // 0..3
    const int row0 = blockIdx.x * 128 + warp * 16 + g;
    const int row1 = row0 + 8;
    const bool r0ok = row0 < n, r1ok = row1 < n;

    float c[32][4];
    #pragma unroll
    for (int t = 0; t < 32; t++) {
        c[t][0] = 0.f; c[t][1] = 0.f; c[t][2] = 0.f; c[t][3] = 0.f;
    }

    const float* x0 = x + (size_t)row0 * F;
    const float* x1 = x + (size_t)row1 * F;

    #pragma unroll
    for (int ks = 0; ks < 16; ks++) {
        const int kb = ks * 8;
        unsigned a0 = r0ok ? f2tf(__ldg(x0 + kb + tk))     : 0u;
        unsigned a1 = r1ok ? f2tf(__ldg(x1 + kb + tk))     : 0u;
        unsigned a2 = r0ok ? f2tf(__ldg(x0 + kb + tk + 4)) : 0u;
        unsigned a3 = r1ok ? f2tf(__ldg(x1 + kb + tk + 4)) : 0u;
        const unsigned* ws0 = Ws + (kb + tk) * WS_STRIDE + g;
        const unsigned* ws1 = ws0 + 4 * WS_STRIDE;
        #pragma unroll
        for (int nt = 0; nt < 32; nt++) {
            unsigned b0 = ws0[nt * 8];
            unsigned b1 = ws1[nt * 8];
            mma_tf32(c[nt], a0, a1, a2, a3, b0, b1);
        }
    }

    // epilogue: add bias, convert to bf16, store
    #pragma unroll
    for (int nt = 0; nt < 32; nt++) {
        int col = nt * 8 + tk * 2;         // 0..254 (even)
        bool isL = (col < 128);
        int lc = isL ? col : col - 128;
        float b0 = __ldg((isL ? bl : br) + lc);
        float b1 = __ldg((isL ? bl : br) + lc + 1);
        __nv_bfloat162* dst = isL ? g_xlb : g_xrb;
        if (r0ok) {
            __nv_bfloat162 h;
            h.x = __float2bfloat16(c[nt][0] + b0);
            h.y = __float2bfloat16(c[nt][1] + b1);
            dst[(size_t)row0 * 64 + (lc >> 1)] = h;
        }
        if (r1ok) {
            __nv_bfloat162 h;
            h.x = __float2bfloat16(c[nt][2] + b0);
            h.y = __float2bfloat16(c[nt][3] + b1);
            dst[(size_t)row1 * 64 + (lc >> 1)] = h;
        }
    }
}

// ---------------- pass 1: per-edge logits + segment max (bf16 gather) -------
__global__ void __launch_bounds__(256) edge_pass1(
    const void* __restrict__ ei_raw, const float* __restrict__ att,
    int nE, int nN)
{
    const int lane   = threadIdx.x & 31;
    const int warp   = (blockIdx.x * blockDim.x + threadIdx.x) >> 5;
    const int nwarps = (gridDim.x * blockDim.x) >> 5;
    const int total  = nE + nN;
    const int is64   = g_is64;
    const long long* e64 = (const long long*)ei_raw;
    const int*       e32 = (const int*)ei_raw;

    const float4 a = reinterpret_cast<const float4*>(att)[lane];
    const uint2* xl2 = reinterpret_cast<const uint2*>(g_xlb);
    const uint2* xr2 = reinterpret_cast<const uint2*>(g_xrb);

    for (int e = warp; e < total; e += nwarps) {
        int s, d;
        if (e < nE) {
            if (is64) { s = (int)e64[e]; d = (int)e64[nE + e]; }
            else      { s = e32[e];      d = e32[nE + e];      }
        } else {
            s = e - nE; d = s;
        }

        uint2 up = xl2[(size_t)s * 32 + lane];
        uint2 vp = xr2[(size_t)d * 32 + lane];
        float2 u0 = __bfloat1622float2(*(__nv_bfloat162*)&up.x);
        float2 u1 = __bfloat1622float2(*(__nv_bfloat162*)&up.y);
        float2 v0 = __bfloat1622float2(*(__nv_bfloat162*)&vp.x);
        float2 v1 = __bfloat1622float2(*(__nv_bfloat162*)&vp.y);

        float z, sum;
        z = u0.x + v0.x; z = z > 0.f ? z : 0.2f * z; sum  = a.x * z;
        z = u0.y + v0.y; z = z > 0.f ? z : 0.2f * z; sum += a.y * z;
        z = u1.x + v1.x; z = z > 0.f ? z : 0.2f * z; sum += a.z * z;
        z = u1.y + v1.y; z = z > 0.f ? z : 0.2f * z; sum += a.w * z;

        #pragma unroll
        for (int off = 16; off > 0; off >>= 1)
            sum += __shfl_xor_sync(0xffffffffu, sum, off);

        if (lane == 0) {
            g_logits[e] = sum;
            g_src[e] = s;
            g_dst[e] = d;
            atomicMax(&g_menc[d], fenc(sum));
        }
    }
}

// ---------------- pass 2 ----------------
__global__ void __launch_bounds__(256) edge_pass2(int total) {
    int e = blockIdx.x * blockDim.x + threadIdx.x;
    if (e >= total) return;
    int d = g_dst[e];
    float m = fdec(g_menc[d]);
    float p = __expf(g_logits[e] - m);
    g_p[e] = p;
    atomicAdd(&g_denom[d], p);
}

// ---------------- pass 3: global weighted sum (bf16 gather, coalesced meta) --
__global__ void __launch_bounds__(256) edge_pass3(int total) {
    __shared__ float sacc[F];
    const int tid = threadIdx.x;
    if (tid < F) sacc[tid] = 0.f;
    __syncthreads();

    const int lane   = tid & 31;
    const int warp   = (blockIdx.x * blockDim.x + tid) >> 5;
    const int nwarps = (gridDim.x * blockDim.x) >> 5;
    const uint2* xl2 = reinterpret_cast<const uint2*>(g_xlb);

    float4 acc = make_float4(0.f, 0.f, 0.f, 0.f);

    for (int e0 = warp * 32; e0 < total; e0 += nwarps * 32) {
        int e = e0 + lane;
        int s = 0; float w = 0.f;
        if (e < total) {
            s = g_src[e];
            w = g_p[e] / g_denom[g_dst[e]];
        }
        int cnt = total - e0; if (cnt > 32) cnt = 32;
        for (int j = 0; j < cnt; j++) {
            int   sj = __shfl_sync(0xffffffffu, s, j);
            float wj = __shfl_sync(0xffffffffu, w, j);
            uint2 up = xl2[(size_t)sj * 32 + lane];
            float2 u0 = __bfloat1622float2(*(__nv_bfloat162*)&up.x);
            float2 u1 = __bfloat1622float2(*(__nv_bfloat162*)&up.y);
            acc.x += wj * u0.x; acc.y += wj * u0.y;
            acc.z += wj * u1.x; acc.w += wj * u1.y;
        }
    }

    atomicAdd(&sacc[lane * 4 + 0], acc.x);
    atomicAdd(&sacc[lane * 4 + 1], acc.y);
    atomicAdd(&sacc[lane * 4 + 2], acc.z);
    atomicAdd(&sacc[lane * 4 + 3], acc.w);
    __syncthreads();
    if (tid < F) atomicAdd(&g_acc[tid], sacc[tid]);
}

// ---------------- finalize ----------------
__global__ void finalize(
    const float* __restrict__ bias1,
    const float* __restrict__ gamma, const float* __restrict__ beta,
    const float* __restrict__ mean,  const float* __restrict__ var,
    const float* __restrict__ Wc,    const float* __restrict__ bc,
    float* __restrict__ out, int nN)
{
    __shared__ float sg[F];
    __shared__ float sl[5];
    const int d = threadIdx.x;

    float gv = g_acc[d] / (float)nN + bias1[d];
    gv = (gv - mean[d]) * rsqrtf(var[d] + 1e-5f) * gamma[d] + beta[d];
    sg[d] = gv;
    __syncthreads();

    if (d < 5) {
        float s = bc[d];
        #pragma unroll 8
        for (int k = 0; k < F; k++) s += sg[k] * Wc[k * 5 + d];
        sl[d] = s;
    }
    __syncthreads();

    if (d == 0) {
        float mx = sl[0];
        #pragma unroll
        for (int c = 1; c < 5; c++) mx = fmaxf(mx, sl[c]);
        float e[5], sum = 0.f;
        #pragma unroll
        for (int c = 0; c < 5; c++) { e[c] = expf(sl[c] - mx); sum += e[c]; }
        #pragma unroll
        for (int c = 0; c < 5; c++) out[c] = e[c] / sum;
    }
}

// ---------------- launch ----------------
extern "C" void kernel_launch(void* const* d_in, const int* in_sizes, int n_in,
                              void* d_out, int out_size)
{
    const float* x     = (const float*)d_in[0];
    const void*  ei    = d_in[1];
    const float* Wl    = (const float*)d_in[2];
    const float* bl    = (const float*)d_in[3];
    const float* Wr    = (const float*)d_in[4];
    const float* br    = (const float*)d_in[5];
    const float* att   = (const float*)d_in[6];
    const float* bias1 = (const float*)d_in[7];
    const float* gamma = (const float*)d_in[8];
    const float* beta  = (const float*)d_in[9];
    const float* mean  = (const float*)d_in[10];
    const float* var   = (const float*)d_in[11];
    const float* Wc    = (const float*)d_in[12];
    const float* bc    = (const float*)d_in[13];
    float* out = (float*)d_out;

    const int nN = in_sizes[0] / F;
    const int nE = in_sizes[1] / 2;
    const int total = nE + nN;

    static int smem_set = 0;
    if (!smem_set) {
        cudaFuncSetAttribute(gemm_tf32,
            cudaFuncAttributeMaxDynamicSharedMemorySize, GEMM_SMEM);
        smem_set = 1;
    }

    detect_dtype<<<1, 1>>>(ei, nE, nN);
    init_kernel<<<(nN + 255) / 256, 256>>>(nN);
    gemm_tf32<<<(nN + 127) / 128, 256, GEMM_SMEM>>>(x, Wl, bl, Wr, br, nN);
    edge_pass1<<<2368, 256>>>(ei, att, nE, nN);
    edge_pass2<<<(total + 255) / 256, 256>>>(total);
    edge_pass3<<<2368, 256>>>(total);
    finalize<<<1, F>>>(bias1, gamma, beta, mean, var, Wc, bc, out, nN);
}

// round 4
// speedup vs baseline: 1.6902x; 1.1819x over previous
#include <cuda_runtime.h>
#include <cuda_bf16.h>
#include <math.h>

#define F 128
#define MAXN 50000
#define MAXE 500000
#define MAXT (MAXE + MAXN)

// ---------------- scratch ----------------
__device__ __nv_bfloat162 g_xlb[(size_t)MAXN * 64];   // xl in bf16 (pairs)
__device__ __nv_bfloat162 g_xrb[(size_t)MAXN * 64];   // xr in bf16 (pairs)
__device__ int2     g_edge[MAXT];                     // normalized (src,dst)
__device__ float    g_p[MAXT];                        // exp(logit)
__device__ float    g_denom[MAXN];                    // sum_p -> 1/sum_p
__device__ float    g_acc[F];

// ---------------- edge normalization (+ per-block dtype detect) -------------
__global__ void __launch_bounds__(256) convert_edges(
    const void* __restrict__ ei_raw, int nE, int nN)
{
    __shared__ int s_is64;
    if (threadIdx.x == 0) {
        const long long* e64 = (const long long*)ei_raw;
        int ok = 1;
        int lim = nE < 64 ? nE : 64;
        for (int i = 0; i < lim; i++) {
            long long v = e64[i];
            if (v < 0 || v >= (long long)nN) { ok = 0; break; }
        }
        s_is64 = ok;
    }
    __syncthreads();
    const int is64 = s_is64;
    const long long* e64 = (const long long*)ei_raw;
    const int*       e32 = (const int*)ei_raw;
    const int total = nE + nN;
    for (int i = blockIdx.x * blockDim.x + threadIdx.x; i < total;
         i += gridDim.x * blockDim.x) {
        int s, d;
        if (i < nE) {
            if (is64) { s = (int)e64[i]; d = (int)e64[nE + i]; }
            else      { s = e32[i];      d = e32[nE + i];      }
        } else {
            s = i - nE; d = s;
        }
        g_edge[i] = make_int2(s, d);
    }
}

// ---------------- init ----------------
__global__ void init_kernel(int nN) {
    int i = blockIdx.x * blockDim.x + threadIdx.x;
    if (i < nN) g_denom[i] = 0.f;
    if (i < F) g_acc[i] = 0.f;
}

// ---------------- tf32 tensor-core GEMM (unchanged from R3) -----------------
__device__ __forceinline__ unsigned f2tf(float f) {
    unsigned r;
    asm("cvt.rna.tf32.f32 %0, %1;" : "=r"(r) : "f"(f));
    return r;
}
__device__ __forceinline__ void mma_tf32(float* c,
    unsigned a0, unsigned a1, unsigned a2, unsigned a3,
    unsigned b0, unsigned b1)
{
    asm volatile(
        "mma.sync.aligned.m16n8k8.row.col.f32.tf32.tf32.f32 "
        "{%0,%1,%2,%3}, {%4,%5,%6,%7}, {%8,%9}, {%0,%1,%2,%3};"
        : "+f"(c[0]), "+f"(c[1]), "+f"(c[2]), "+f"(c[3])
        : "r"(a0), "r"(a1), "r"(a2), "r"(a3), "r"(b0), "r"(b1));
}

#define WS_STRIDE 264
#define GEMM_SMEM (128 * WS_STRIDE * 4)

__global__ void __launch_bounds__(256) gemm_tf32(
    const float* __restrict__ x,
    const float* __restrict__ Wl, const float* __restrict__ bl,
    const float* __restrict__ Wr, const float* __restrict__ br,
    int n)
{
    extern __shared__ unsigned Ws[];   // [128][264] tf32 words
    const int tid = threadIdx.x;

    for (int i = tid; i < 128 * 256; i += 256) {
        int k = i >> 8, nn = i & 255;
        float v = (nn < 128) ? Wl[k * 128 + nn] : Wr[k * 128 + (nn - 128)];
        Ws[k * WS_STRIDE + nn] = f2tf(v);
    }
    __syncthreads();

    const int warp = tid >> 5, lane = tid & 31;
    const int g  = lane >> 2;
    const int tk = lane & 3;
    const int row0 = blockIdx.x * 128 + warp * 16 + g;
    const int row1 = row0 + 8;
    const bool r0ok = row0 < n, r1ok = row1 < n;

    float c[32][4];
    #pragma unroll
    for (int t = 0; t < 32; t++) {
        c[t][0] = 0.f; c[t][1] = 0.f; c[t][2] = 0.f; c[t][3] = 0.f;
    }

    const float* x0 = x + (size_t)row0 * F;
    const float* x1 = x + (size_t)row1 * F;

    #pragma unroll
    for (int ks = 0; ks < 16; ks++) {
        const int kb = ks * 8;
        unsigned a0 = r0ok ? f2tf(__ldg(x0 + kb + tk))     : 0u;
        unsigned a1 = r1ok ? f2tf(__ldg(x1 + kb + tk))     : 0u;
        unsigned a2 = r0ok ? f2tf(__ldg(x0 + kb + tk + 4)) : 0u;
        unsigned a3 = r1ok ? f2tf(__ldg(x1 + kb + tk + 4)) : 0u;
        const unsigned* ws0 = Ws + (kb + tk) * WS_STRIDE + g;
        const unsigned* ws1 = ws0 + 4 * WS_STRIDE;
        #pragma unroll
        for (int nt = 0; nt < 32; nt++) {
            unsigned b0 = ws0[nt * 8];
            unsigned b1 = ws1[nt * 8];
            mma_tf32(c[nt], a0, a1, a2, a3, b0, b1);
        }
    }

    #pragma unroll
    for (int nt = 0; nt < 32; nt++) {
        int col = nt * 8 + tk * 2;
        bool isL = (col < 128);
        int lc = isL ? col : col - 128;
        float b0 = __ldg((isL ? bl : br) + lc);
        float b1 = __ldg((isL ? bl : br) + lc + 1);
        __nv_bfloat162* dst = isL ? g_xlb : g_xrb;
        if (r0ok) {
            __nv_bfloat162 h;
            h.x = __float2bfloat16(c[nt][0] + b0);
            h.y = __float2bfloat16(c[nt][1] + b1);
            dst[(size_t)row0 * 64 + (lc >> 1)] = h;
        }
        if (r1ok) {
            __nv_bfloat162 h;
            h.x = __float2bfloat16(c[nt][2] + b0);
            h.y = __float2bfloat16(c[nt][3] + b1);
            dst[(size_t)row1 * 64 + (lc >> 1)] = h;
        }
    }
}

// ---------------- pass 1: logits + exp + denom (fused, no max) --------------
// 16 lanes/edge, 2 edges/warp. Lane covers 8 dims (one uint4 = 8 bf16).
__global__ void __launch_bounds__(256) edge_pass1(
    const float* __restrict__ att, int total)
{
    const int lane = threadIdx.x & 31;
    const int sub  = lane & 15;           // lane within half-warp
    const int half = lane >> 4;           // which edge of the pair
    const int warp   = (blockIdx.x * blockDim.x + threadIdx.x) >> 5;
    const int nwarps = (gridDim.x * blockDim.x) >> 5;
    const int npairs = (total + 1) >> 1;

    const float4 a0 = reinterpret_cast<const float4*>(att)[sub * 2];
    const float4 a1 = reinterpret_cast<const float4*>(att)[sub * 2 + 1];
    const uint4* xl4 = reinterpret_cast<const uint4*>(g_xlb);
    const uint4* xr4 = reinterpret_cast<const uint4*>(g_xrb);

    for (int pr = warp; pr < npairs; pr += nwarps) {
        const int e = pr * 2 + half;
        const bool ok = e < total;
        int2 ed = ok ? g_edge[e] : make_int2(0, 0);

        uint4 up = xl4[(size_t)ed.x * 16 + sub];
        uint4 vp = xr4[(size_t)ed.y * 16 + sub];

        __nv_bfloat162 z0 = __hadd2(*(__nv_bfloat162*)&up.x, *(__nv_bfloat162*)&vp.x);
        __nv_bfloat162 z1 = __hadd2(*(__nv_bfloat162*)&up.y, *(__nv_bfloat162*)&vp.y);
        __nv_bfloat162 z2 = __hadd2(*(__nv_bfloat162*)&up.z, *(__nv_bfloat162*)&vp.z);
        __nv_bfloat162 z3 = __hadd2(*(__nv_bfloat162*)&up.w, *(__nv_bfloat162*)&vp.w);
        float2 f0 = __bfloat1622float2(z0);
        float2 f1 = __bfloat1622float2(z1);
        float2 f2 = __bfloat1622float2(z2);
        float2 f3 = __bfloat1622float2(z3);

        float sum;
        sum  = a0.x * fmaxf(f0.x, 0.2f * f0.x);
        sum += a0.y * fmaxf(f0.y, 0.2f * f0.y);
        sum += a0.z * fmaxf(f1.x, 0.2f * f1.x);
        sum += a0.w * fmaxf(f1.y, 0.2f * f1.y);
        sum += a1.x * fmaxf(f2.x, 0.2f * f2.x);
        sum += a1.y * fmaxf(f2.y, 0.2f * f2.y);
        sum += a1.z * fmaxf(f3.x, 0.2f * f3.x);
        sum += a1.w * fmaxf(f3.y, 0.2f * f3.y);

        // reduce within half-warp (xor <= 15 stays inside the half)
        #pragma unroll
        for (int off = 8; off > 0; off >>= 1)
            sum += __shfl_xor_sync(0xffffffffu, sum, off);

        if (sub == 0 && ok) {
            float p = __expf(fminf(fmaxf(sum, -60.f), 60.f));
            g_p[e] = p;
            atomicAdd(&g_denom[ed.y], p);
        }
    }
}

// ---------------- reciprocal of denom ----------------
__global__ void recip_kernel(int nN) {
    int i = blockIdx.x * blockDim.x + threadIdx.x;
    if (i < nN) g_denom[i] = 1.0f / g_denom[i];
}

// ---------------- pass 3: global weighted sum ----------------
__global__ void __launch_bounds__(256) edge_pass3(int total) {
    __shared__ float sacc[F];
    const int tid = threadIdx.x;
    if (tid < F) sacc[tid] = 0.f;
    __syncthreads();

    const int lane = tid & 31;
    const int sub  = lane & 15;
    const int half = lane >> 4;
    const int warp   = (blockIdx.x * blockDim.x + tid) >> 5;
    const int nwarps = (gridDim.x * blockDim.x) >> 5;
    const int npairs = (total + 1) >> 1;
    const uint4* xl4 = reinterpret_cast<const uint4*>(g_xlb);

    float acc[8];
    #pragma unroll
    for (int k = 0; k < 8; k++) acc[k] = 0.f;

    for (int pr = warp; pr < npairs; pr += nwarps) {
        const int e = pr * 2 + half;
        const bool ok = e < total;
        int2 ed = ok ? g_edge[e] : make_int2(0, 0);
        float w = ok ? g_p[e] * g_denom[ed.y] : 0.f;

        uint4 up = xl4[(size_t)ed.x * 16 + sub];
        float2 f0 = __bfloat1622float2(*(__nv_bfloat162*)&up.x);
        float2 f1 = __bfloat1622float2(*(__nv_bfloat162*)&up.y);
        float2 f2 = __bfloat1622float2(*(__nv_bfloat162*)&up.z);
        float2 f3 = __bfloat1622float2(*(__nv_bfloat162*)&up.w);
        acc[0] += w * f0.x; acc[1] += w * f0.y;
        acc[2] += w * f1.x; acc[3] += w * f1.y;
        acc[4] += w * f2.x; acc[5] += w * f2.y;
        acc[6] += w * f3.x; acc[7] += w * f3.y;
    }

    // combine the two halves (same dims), then lanes 0-15 commit
    #pragma unroll
    for (int k = 0; k < 8; k++)
        acc[k] += __shfl_xor_sync(0xffffffffu, acc[k], 16);
    if (half == 0) {
        #pragma unroll
        for (int k = 0; k < 8; k++)
            atomicAdd(&sacc[sub * 8 + k], acc[k]);
    }
    __syncthreads();
    if (tid < F) atomicAdd(&g_acc[tid], sacc[tid]);
}

// ---------------- finalize ----------------
__global__ void finalize(
    const float* __restrict__ bias1,
    const float* __restrict__ gamma, const float* __restrict__ beta,
    const float* __restrict__ mean,  const float* __restrict__ var,
    const float* __restrict__ Wc,    const float* __restrict__ bc,
    float* __restrict__ out, int nN)
{
    __shared__ float sg[F];
    __shared__ float sl[5];
    const int d = threadIdx.x;

    float gv = g_acc[d] / (float)nN + bias1[d];
    gv = (gv - mean[d]) * rsqrtf(var[d] + 1e-5f) * gamma[d] + beta[d];
    sg[d] = gv;
    __syncthreads();

    if (d < 5) {
        float s = bc[d];
        #pragma unroll 8
        for (int k = 0; k < F; k++) s += sg[k] * Wc[k * 5 + d];
        sl[d] = s;
    }
    __syncthreads();

    if (d == 0) {
        float mx = sl[0];
        #pragma unroll
        for (int c = 1; c < 5; c++) mx = fmaxf(mx, sl[c]);
        float e[5], sum = 0.f;
        #pragma unroll
        for (int c = 0; c < 5; c++) { e[c] = expf(sl[c] - mx); sum += e[c]; }
        #pragma unroll
        for (int c = 0; c < 5; c++) out[c] = e[c] / sum;
    }
}

// ---------------- launch ----------------
extern "C" void kernel_launch(void* const* d_in, const int* in_sizes, int n_in,
                              void* d_out, int out_size)
{
    const float* x     = (const float*)d_in[0];
    const void*  ei    = d_in[1];
    const float* Wl    = (const float*)d_in[2];
    const float* bl    = (const float*)d_in[3];
    const float* Wr    = (const float*)d_in[4];
    const float* br    = (const float*)d_in[5];
    const float* att   = (const float*)d_in[6];
    const float* bias1 = (const float*)d_in[7];
    const float* gamma = (const float*)d_in[8];
    const float* beta  = (const float*)d_in[9];
    const float* mean  = (const float*)d_in[10];
    const float* var   = (const float*)d_in[11];
    const float* Wc    = (const float*)d_in[12];
    const float* bc    = (const float*)d_in[13];
    float* out = (float*)d_out;

    const int nN = in_sizes[0] / F;
    const int nE = in_sizes[1] / 2;
    const int total = nE + nN;

    static int smem_set = 0;
    if (!smem_set) {
        cudaFuncSetAttribute(gemm_tf32,
            cudaFuncAttributeMaxDynamicSharedMemorySize, GEMM_SMEM);
        smem_set = 1;
    }

    convert_edges<<<592, 256>>>(ei, nE, nN);
    init_kernel<<<(nN + 255) / 256, 256>>>(nN);
    gemm_tf32<<<(nN + 127) / 128, 256, GEMM_SMEM>>>(x, Wl, bl, Wr, br, nN);
    edge_pass1<<<2368, 256>>>(att, total);
    recip_kernel<<<(nN + 255) / 256, 256>>>(nN);
    edge_pass3<<<2368, 256>>>(total);
    finalize<<<1, F>>>(bias1, gamma, beta, mean, var, Wc, bc, out, nN);
}

// round 5
// speedup vs baseline: 2.1067x; 1.2465x over previous
#include <cuda_runtime.h>
#include <cuda_bf16.h>
#include <math.h>

#define F 128
#define MAXN 50000
#define MAXE 500000
#define MAXT (MAXE + MAXN)

// ---------------- scratch ----------------
__device__ __nv_bfloat162 g_xlb[(size_t)MAXN * 64];   // xl in bf16 (pairs)
__device__ __nv_bfloat162 g_xrb[(size_t)MAXN * 64];   // xr in bf16 (pairs)
__device__ int2     g_edge[MAXT];                     // normalized (src,dst)
__device__ float    g_p[MAXT];                        // exp(logit)
__device__ float    g_denom[MAXN];                    // sum_p -> 1/sum_p
__device__ float    g_acc[F];
__device__ int      g_is64;

// ---------------- dtype detection (1 warp, parallel) ----------------
__global__ void detect_dtype(const void* __restrict__ ei, int nE, int nN) {
    const long long* e64 = (const long long*)ei;
    const int lane = threadIdx.x;
    const int lim = nE < 64 ? nE : 64;
    int bad = 0;
    for (int i = lane; i < lim; i += 32) {
        long long v = e64[i];
        if (v < 0 || v >= (long long)nN) bad = 1;
    }
    unsigned m = __ballot_sync(0xffffffffu, bad);
    if (lane == 0) g_is64 = (m == 0) ? 1 : 0;
}

// ---------------- edge normalization + init (fused) ----------------
__global__ void __launch_bounds__(256) convert_edges(
    const void* __restrict__ ei_raw, int nE, int nN)
{
    const int is64 = g_is64;
    const long long* e64 = (const long long*)ei_raw;
    const int*       e32 = (const int*)ei_raw;
    const int total = nE + nN;
    const int gsz = gridDim.x * blockDim.x;
    for (int i = blockIdx.x * blockDim.x + threadIdx.x; i < total; i += gsz) {
        int s, d;
        if (i < nE) {
            if (is64) { s = (int)e64[i]; d = (int)e64[nE + i]; }
            else      { s = e32[i];      d = e32[nE + i];      }
        } else {
            s = i - nE; d = s;
        }
        g_edge[i] = make_int2(s, d);
        if (i < nN) g_denom[i] = 0.f;
        if (i < F)  g_acc[i] = 0.f;
    }
}

// ---------------- tf32 tensor-core GEMM (persistent) ----------------
__device__ __forceinline__ unsigned f2tf(float f) {
    unsigned r;
    asm("cvt.rna.tf32.f32 %0, %1;" : "=r"(r) : "f"(f));
    return r;
}
__device__ __forceinline__ void mma_tf32(float* c,
    unsigned a0, unsigned a1, unsigned a2, unsigned a3,
    unsigned b0, unsigned b1)
{
    asm volatile(
        "mma.sync.aligned.m16n8k8.row.col.f32.tf32.tf32.f32 "
        "{%0,%1,%2,%3}, {%4,%5,%6,%7}, {%8,%9}, {%0,%1,%2,%3};"
        : "+f"(c[0]), "+f"(c[1]), "+f"(c[2]), "+f"(c[3])
        : "r"(a0), "r"(a1), "r"(a2), "r"(a3), "r"(b0), "r"(b1));
}

#define WS_STRIDE 264
#define GEMM_SMEM (128 * WS_STRIDE * 4)
#define GEMM_GRID 148

__global__ void __launch_bounds__(256) gemm_tf32(
    const float* __restrict__ x,
    const float* __restrict__ Wl, const float* __restrict__ bl,
    const float* __restrict__ Wr, const float* __restrict__ br,
    int n, int ntiles)
{
    extern __shared__ unsigned Ws[];   // [128][264] tf32 words
    const int tid = threadIdx.x;

    // stage W = [Wl | Wr] as tf32, vectorized (float4 in, uint4 out)
    const float4* Wl4 = reinterpret_cast<const float4*>(Wl);
    const float4* Wr4 = reinterpret_cast<const float4*>(Wr);
    for (int i = tid; i < 128 * 64; i += 256) {
        int k = i >> 6, q = i & 63;
        float4 v = (q < 32) ? Wl4[k * 32 + q] : Wr4[k * 32 + (q - 32)];
        uint4 w = make_uint4(f2tf(v.x), f2tf(v.y), f2tf(v.z), f2tf(v.w));
        *reinterpret_cast<uint4*>(&Ws[k * WS_STRIDE + q * 4]) = w;
    }
    __syncthreads();

    const int warp = tid >> 5, lane = tid & 31;
    const int g  = lane >> 2;
    const int tk = lane & 3;

    for (int tile = blockIdx.x; tile < ntiles; tile += gridDim.x) {
        const int row0 = tile * 128 + warp * 16 + g;
        const int row1 = row0 + 8;
        const bool r0ok = row0 < n, r1ok = row1 < n;

        float c[32][4];
        #pragma unroll
        for (int t = 0; t < 32; t++) {
            c[t][0] = 0.f; c[t][1] = 0.f; c[t][2] = 0.f; c[t][3] = 0.f;
        }

        const float* x0 = x + (size_t)row0 * F;
        const float* x1 = x + (size_t)row1 * F;

        #pragma unroll
        for (int ks = 0; ks < 16; ks++) {
            const int kb = ks * 8;
            // raw fp32 bits: HW truncates to tf32 (<=2^-11 rel err, fine)
            unsigned a0 = r0ok ? __float_as_uint(__ldg(x0 + kb + tk))     : 0u;
            unsigned a1 = r1ok ? __float_as_uint(__ldg(x1 + kb + tk))     : 0u;
            unsigned a2 = r0ok ? __float_as_uint(__ldg(x0 + kb + tk + 4)) : 0u;
            unsigned a3 = r1ok ? __float_as_uint(__ldg(x1 + kb + tk + 4)) : 0u;
            const unsigned* ws0 = Ws + (kb + tk) * WS_STRIDE + g;
            const unsigned* ws1 = ws0 + 4 * WS_STRIDE;
            #pragma unroll
            for (int nt = 0; nt < 32; nt++) {
                unsigned b0 = ws0[nt * 8];
                unsigned b1 = ws1[nt * 8];
                mma_tf32(c[nt], a0, a1, a2, a3, b0, b1);
            }
        }

        #pragma unroll
        for (int nt = 0; nt < 32; nt++) {
            int col = nt * 8 + tk * 2;
            bool isL = (col < 128);
            int lc = isL ? col : col - 128;
            float b0 = __ldg((isL ? bl : br) + lc);
            float b1 = __ldg((isL ? bl : br) + lc + 1);
            __nv_bfloat162* dst = isL ? g_xlb : g_xrb;
            if (r0ok) {
                __nv_bfloat162 h;
                h.x = __float2bfloat16(c[nt][0] + b0);
                h.y = __float2bfloat16(c[nt][1] + b1);
                dst[(size_t)row0 * 64 + (lc >> 1)] = h;
            }
            if (r1ok) {
                __nv_bfloat162 h;
                h.x = __float2bfloat16(c[nt][2] + b0);
                h.y = __float2bfloat16(c[nt][3] + b1);
                dst[(size_t)row1 * 64 + (lc >> 1)] = h;
            }
        }
    }
}

// ---------------- pass 1: logits + exp + denom (packed bf16 math) -----------
// 16 lanes/edge, 2 edges/warp. Lane covers 8 dims (one uint4 = 8 bf16).
__global__ void __launch_bounds__(256) edge_pass1(
    const float* __restrict__ att, int total)
{
    const int lane = threadIdx.x & 31;
    const int sub  = lane & 15;
    const int half = lane >> 4;
    const int warp   = (blockIdx.x * blockDim.x + threadIdx.x) >> 5;
    const int nwarps = (gridDim.x * blockDim.x) >> 5;
    const int npairs = (total + 1) >> 1;

    const float4 a0 = reinterpret_cast<const float4*>(att)[sub * 2];
    const float4 a1 = reinterpret_cast<const float4*>(att)[sub * 2 + 1];
    const __nv_bfloat162 at0 = __floats2bfloat162_rn(a0.x, a0.y);
    const __nv_bfloat162 at1 = __floats2bfloat162_rn(a0.z, a0.w);
    const __nv_bfloat162 at2 = __floats2bfloat162_rn(a1.x, a1.y);
    const __nv_bfloat162 at3 = __floats2bfloat162_rn(a1.z, a1.w);
    const __nv_bfloat162 c02 = __float2bfloat162_rn(0.2f);
    const __nv_bfloat162 zero = __float2bfloat162_rn(0.f);

    const uint4* xl4 = reinterpret_cast<const uint4*>(g_xlb);
    const uint4* xr4 = reinterpret_cast<const uint4*>(g_xrb);

    for (int pr = warp; pr < npairs; pr += nwarps) {
        const int e = pr * 2 + half;
        const bool ok = e < total;
        int2 ed = ok ? g_edge[e] : make_int2(0, 0);

        uint4 up = xl4[(unsigned)ed.x * 16u + sub];
        uint4 vp = xr4[(unsigned)ed.y * 16u + sub];

        __nv_bfloat162 acc = zero;
        __nv_bfloat162 z;
        z = __hadd2(*(__nv_bfloat162*)&up.x, *(__nv_bfloat162*)&vp.x);
        z = __hmax2(z, __hmul2(z, c02));
        acc = __hfma2(at0, z, acc);
        z = __hadd2(*(__nv_bfloat162*)&up.y, *(__nv_bfloat162*)&vp.y);
        z = __hmax2(z, __hmul2(z, c02));
        acc = __hfma2(at1, z, acc);
        z = __hadd2(*(__nv_bfloat162*)&up.z, *(__nv_bfloat162*)&vp.z);
        z = __hmax2(z, __hmul2(z, c02));
        acc = __hfma2(at2, z, acc);
        z = __hadd2(*(__nv_bfloat162*)&up.w, *(__nv_bfloat162*)&vp.w);
        z = __hmax2(z, __hmul2(z, c02));
        acc = __hfma2(at3, z, acc);

        float2 s2 = __bfloat1622float2(acc);
        float sum = s2.x + s2.y;

        #pragma unroll
        for (int off = 8; off > 0; off >>= 1)
            sum += __shfl_xor_sync(0xffffffffu, sum, off);

        if (sub == 0 && ok) {
            float p = __expf(fminf(fmaxf(sum, -60.f), 60.f));
            g_p[e] = p;
            atomicAdd(&g_denom[ed.y], p);
        }
    }
}

// ---------------- reciprocal of denom ----------------
__global__ void recip_kernel(int nN) {
    int i = blockIdx.x * blockDim.x + threadIdx.x;
    if (i < nN) g_denom[i] = 1.0f / g_denom[i];
}

// ---------------- pass 3: global weighted sum (bf16 gather, f32 acc) --------
__global__ void __launch_bounds__(256) edge_pass3(int total) {
    __shared__ float sacc[F];
    const int tid = threadIdx.x;
    if (tid < F) sacc[tid] = 0.f;
    __syncthreads();

    const int lane = tid & 31;
    const int sub  = lane & 15;
    const int half = lane >> 4;
    const int warp   = (blockIdx.x * blockDim.x + tid) >> 5;
    const int nwarps = (gridDim.x * blockDim.x) >> 5;
    const int npairs = (total + 1) >> 1;
    const uint4* xl4 = reinterpret_cast<const uint4*>(g_xlb);

    float acc[8];
    #pragma unroll
    for (int k = 0; k < 8; k++) acc[k] = 0.f;

    for (int pr = warp; pr < npairs; pr += nwarps) {
        const int e = pr * 2 + half;
        const bool ok = e < total;
        int2 ed = ok ? g_edge[e] : make_int2(0, 0);
        float w = ok ? g_p[e] * g_denom[ed.y] : 0.f;

        uint4 up = xl4[(unsigned)ed.x * 16u + sub];
        float2 f0 = __bfloat1622float2(*(__nv_bfloat162*)&up.x);
        float2 f1 = __bfloat1622float2(*(__nv_bfloat162*)&up.y);
        float2 f2 = __bfloat1622float2(*(__nv_bfloat162*)&up.z);
        float2 f3 = __bfloat1622float2(*(__nv_bfloat162*)&up.w);
        acc[0] += w * f0.x; acc[1] += w * f0.y;
        acc[2] += w * f1.x; acc[3] += w * f1.y;
        acc[4] += w * f2.x; acc[5] += w * f2.y;
        acc[6] += w * f3.x; acc[7] += w * f3.y;
    }

    #pragma unroll
    for (int k = 0; k < 8; k++)
        acc[k] += __shfl_xor_sync(0xffffffffu, acc[k], 16);
    if (half == 0) {
        #pragma unroll
        for (int k = 0; k < 8; k++)
            atomicAdd(&sacc[sub * 8 + k], acc[k]);
    }
    __syncthreads();
    if (tid < F) atomicAdd(&g_acc[tid], sacc[tid]);
}

// ---------------- finalize ----------------
__global__ void finalize(
    const float* __restrict__ bias1,
    const float* __restrict__ gamma, const float* __restrict__ beta,
    const float* __restrict__ mean,  const float* __restrict__ var,
    const float* __restrict__ Wc,    const float* __restrict__ bc,
    float* __restrict__ out, int nN)
{
    __shared__ float sg[F];
    __shared__ float sl[5];
    const int d = threadIdx.x;

    float gv = g_acc[d] / (float)nN + bias1[d];
    gv = (gv - mean[d]) * rsqrtf(var[d] + 1e-5f) * gamma[d] + beta[d];
    sg[d] = gv;
    __syncthreads();

    if (d < 5) {
        float s = bc[d];
        #pragma unroll 8
        for (int k = 0; k < F; k++) s += sg[k] * Wc[k * 5 + d];
        sl[d] = s;
    }
    __syncthreads();

    if (d == 0) {
        float mx = sl[0];
        #pragma unroll
        for (int c = 1; c < 5; c++) mx = fmaxf(mx, sl[c]);
        float e[5], sum = 0.f;
        #pragma unroll
        for (int c = 0; c < 5; c++) { e[c] = expf(sl[c] - mx); sum += e[c]; }
        #pragma unroll
        for (int c = 0; c < 5; c++) out[c] = e[c] / sum;
    }
}

// ---------------- launch ----------------
extern "C" void kernel_launch(void* const* d_in, const int* in_sizes, int n_in,
                              void* d_out, int out_size)
{
    const float* x     = (const float*)d_in[0];
    const void*  ei    = d_in[1];
    const float* Wl    = (const float*)d_in[2];
    const float* bl    = (const float*)d_in[3];
    const float* Wr    = (const float*)d_in[4];
    const float* br    = (const float*)d_in[5];
    const float* att   = (const float*)d_in[6];
    const float* bias1 = (const float*)d_in[7];
    const float* gamma = (const float*)d_in[8];
    const float* beta  = (const float*)d_in[9];
    const float* mean  = (const float*)d_in[10];
    const float* var   = (const float*)d_in[11];
    const float* Wc    = (const float*)d_in[12];
    const float* bc    = (const float*)d_in[13];
    float* out = (float*)d_out;

    const int nN = in_sizes[0] / F;
    const int nE = in_sizes[1] / 2;
    const int total = nE + nN;
    const int ntiles = (nN + 127) / 128;

    static int smem_set = 0;
    if (!smem_set) {
        cudaFuncSetAttribute(gemm_tf32,
            cudaFuncAttributeMaxDynamicSharedMemorySize, GEMM_SMEM);
        smem_set = 1;
    }

    detect_dtype<<<1, 32>>>(ei, nE, nN);
    convert_edges<<<(total + 255) / 256, 256>>>(ei, nE, nN);
    gemm_tf32<<<GEMM_GRID, 256, GEMM_SMEM>>>(x, Wl, bl, Wr, br, nN, ntiles);
    edge_pass1<<<2368, 256>>>(att, total);
    recip_kernel<<<(nN + 255) / 256, 256>>>(nN);
    edge_pass3<<<2368, 256>>>(total);
    finalize<<<1, F>>>(bias1, gamma, beta, mean, var, Wc, bc, out, nN);
}